// round 1
// baseline (speedup 1.0000x reference)
#include <cuda_runtime.h>
#include <cuda_bf16.h>
#include <math.h>

// Problem constants
#define BATCH   128
#define NT      512
#define NC      512
#define EMB     256
#define DK      60
#define DV      60
#define NTOK    (BATCH * NT)    // 65536 query tokens
#define NCTOK   (BATCH * NC)    // 65536 context tokens
#define EPSV    1e-6f

// ---------------------------------------------------------------------------
// Scratch (static device arrays: allocation-free)
// ---------------------------------------------------------------------------
__device__ float g_q [NTOK  * DK];   // 15.7 MB
__device__ float g_k [NCTOK * DK];
__device__ float g_v [NCTOK * DV];
__device__ float g_qn[NTOK];
__device__ float g_kn[NCTOK];

// ---------------------------------------------------------------------------
// Kernel 1: gather tvec rows + project to q (60) + row norms
// block (64, 4), 32 tokens / block, grid 2048
// smem: Wt[256][64] (64KB) + emb[32][256] (32KB) + npart[32][2]
// ---------------------------------------------------------------------------
__global__ void __launch_bounds__(256) proj_q_kernel(
    const int* __restrict__ items, const float* __restrict__ tvec,
    const float* __restrict__ W, const float* __restrict__ bias)
{
    extern __shared__ float sm[];
    float* Wt    = sm;                  // [256][64]
    float* emb   = sm + 256 * 64;       // [32][256]
    float* npart = emb + 32 * 256;      // [32][2]

    const int x = threadIdx.x;          // 0..63 : output index j
    const int g = threadIdx.y;          // 0..3  : token group
    const int tid = g * 64 + x;

    for (int idx = tid; idx < 256 * 64; idx += 256) {
        int k = idx >> 6, j = idx & 63;
        Wt[idx] = (j < DK) ? W[j * EMB + k] : 0.f;
    }

    const int base = blockIdx.x * 32;
    // load 8 embedding rows for this group (coalesced float4)
    for (int rr = 0; rr < 8; rr++) {
        int tok = base + g * 8 + rr;
        int it  = items[tok];
        const float4* src = (const float4*)(tvec + (size_t)it * EMB);
        ((float4*)(emb + (g * 8 + rr) * EMB))[x] = src[x];
    }
    __syncthreads();

    const float bj = (x < DK) ? bias[x] : 0.f;
    float acc[8];
#pragma unroll
    for (int rr = 0; rr < 8; rr++) acc[rr] = 0.f;

    for (int k = 0; k < EMB; k += 4) {
        float w0 = Wt[(k + 0) * 64 + x];
        float w1 = Wt[(k + 1) * 64 + x];
        float w2 = Wt[(k + 2) * 64 + x];
        float w3 = Wt[(k + 3) * 64 + x];
#pragma unroll
        for (int rr = 0; rr < 8; rr++) {
            float4 e = *(const float4*)(emb + (g * 8 + rr) * EMB + k);
            acc[rr] = fmaf(e.x, w0, acc[rr]);
            acc[rr] = fmaf(e.y, w1, acc[rr]);
            acc[rr] = fmaf(e.z, w2, acc[rr]);
            acc[rr] = fmaf(e.w, w3, acc[rr]);
        }
    }

    const int lane = x & 31, wi = x >> 5;
#pragma unroll
    for (int rr = 0; rr < 8; rr++) {
        float v = acc[rr] + bj;
        int tok = base + g * 8 + rr;
        if (x < DK) g_q[(size_t)tok * DK + x] = v;
        float sq = (x < DK) ? v * v : 0.f;
#pragma unroll
        for (int o = 16; o; o >>= 1) sq += __shfl_xor_sync(0xffffffffu, sq, o);
        if (lane == 0) npart[(g * 8 + rr) * 2 + wi] = sq;
    }
    __syncthreads();
    if (tid < 32) {
        int tok = base + tid;
        g_qn[tok] = sqrtf(npart[tid * 2 + 0] + npart[tid * 2 + 1]);
    }
}

// ---------------------------------------------------------------------------
// Kernel 2: gather cvec rows + project to k (60) and v (60) + k norms
// block (128, 2), 16 tokens / block, grid 4096
// smem: Wt[256][128] (128KB) + emb[16][256] (16KB) + npart[16][2]
//   Wt cols: j<60 -> Ac (k proj), 64<=j<124 -> Bc (v proj)
// ---------------------------------------------------------------------------
__global__ void __launch_bounds__(256) proj_kv_kernel(
    const int* __restrict__ items, const float* __restrict__ cvec,
    const float* __restrict__ Wk, const float* __restrict__ bk,
    const float* __restrict__ Wv, const float* __restrict__ bv)
{
    extern __shared__ float sm[];
    float* Wt    = sm;                   // [256][128]
    float* emb   = sm + 256 * 128;       // [16][256]
    float* npart = emb + 16 * 256;       // [16][2]

    const int x = threadIdx.x;           // 0..127
    const int g = threadIdx.y;           // 0..1
    const int tid = g * 128 + x;

    for (int idx = tid; idx < 256 * 128; idx += 256) {
        int k = idx >> 7, j = idx & 127;
        float w = 0.f;
        if (j < DK)                 w = Wk[j * EMB + k];
        else if (j >= 64 && j < 64 + DV) w = Wv[(j - 64) * EMB + k];
        Wt[idx] = w;
    }

    const int base = blockIdx.x * 16;
    // 128 threads load 2 rows per pass (64 float4 each)
    for (int rr2 = 0; rr2 < 4; rr2++) {
        int rr = rr2 * 2 + (x >> 6);
        int xx = x & 63;
        int tok = base + g * 8 + rr;
        int it  = items[tok];
        ((float4*)(emb + (g * 8 + rr) * EMB))[xx] =
            ((const float4*)(cvec + (size_t)it * EMB))[xx];
    }
    __syncthreads();

    float bj = 0.f;
    if (x < DK) bj = bk[x];
    else if (x >= 64 && x < 64 + DV) bj = bv[x - 64];

    float acc[8];
#pragma unroll
    for (int rr = 0; rr < 8; rr++) acc[rr] = 0.f;

    for (int k = 0; k < EMB; k += 4) {
        float w0 = Wt[(k + 0) * 128 + x];
        float w1 = Wt[(k + 1) * 128 + x];
        float w2 = Wt[(k + 2) * 128 + x];
        float w3 = Wt[(k + 3) * 128 + x];
#pragma unroll
        for (int rr = 0; rr < 8; rr++) {
            float4 e = *(const float4*)(emb + (g * 8 + rr) * EMB + k);
            acc[rr] = fmaf(e.x, w0, acc[rr]);
            acc[rr] = fmaf(e.y, w1, acc[rr]);
            acc[rr] = fmaf(e.z, w2, acc[rr]);
            acc[rr] = fmaf(e.w, w3, acc[rr]);
        }
    }

    const int lane = x & 31, wi = x >> 5;
#pragma unroll
    for (int rr = 0; rr < 8; rr++) {
        float v = acc[rr] + bj;
        int tok = base + g * 8 + rr;
        if (x < DK)                      g_k[(size_t)tok * DK + x]        = v;
        else if (x >= 64 && x < 64 + DV) g_v[(size_t)tok * DV + (x - 64)] = v;
        if (wi < 2) {   // warp-uniform: only j<64 warps contribute to k-norm
            float sq = (x < DK) ? v * v : 0.f;
#pragma unroll
            for (int o = 16; o; o >>= 1) sq += __shfl_xor_sync(0xffffffffu, sq, o);
            if (lane == 0) npart[(g * 8 + rr) * 2 + wi] = sq;
        }
    }
    __syncthreads();
    if (tid < 16) {
        int tok = base + tid;
        g_kn[tok] = sqrtf(npart[tid * 2 + 0] + npart[tid * 2 + 1]);
    }
}

// ---------------------------------------------------------------------------
// Kernel 3: fused cosine attention + softmax + P@V + output projection
// grid (NT/128, B) = (4, 128), block 512
// per block: 128 query rows x full 512 context (4 tiles of 128)
// smem: s_s[128][132] | kv-region(max(kt[128][68]+vt[128][64], Rs[256][68]))
//       | kn[128] | pb[128]   == 138240 B
// ---------------------------------------------------------------------------
#define S_PAD  132
#define K_PAD  68
#define V_PAD  64
#define R_PAD  68

__global__ void __launch_bounds__(512) attn_kernel(
    const float* __restrict__ pos_bias,
    const float* __restrict__ R_w, const float* __restrict__ R_b,
    float* __restrict__ out)
{
    extern __shared__ float sm[];
    float* s_s  = sm;                       // [128][132]  (reused as ao[128][68])
    float* kv   = sm + 128 * S_PAD;         // union region (17408 floats)
    float* kt   = kv;                       // [128][68]
    float* vt   = kv + 128 * K_PAD;         // [128][64]
    float* Rs   = kv;                       // [256][68]  (after attention loop)
    float* kn_s = kv + 17408;               // [128]
    float* pb_s = kn_s + 128;               // [128]

    const int b   = blockIdx.y;
    const int tq0 = blockIdx.x * 128;
    const int tid = threadIdx.x;
    const int r   = tid >> 2;               // query row 0..127
    const int c0  = tid & 3;                // c offset / dv chunk

    const size_t qtok = (size_t)b * NT + tq0 + r;
    float4 qreg[15];
    {
        const float4* qp = (const float4*)(g_q + qtok * DK);
#pragma unroll
        for (int kk = 0; kk < 15; kk++) qreg[kk] = qp[kk];
    }
    const float qn = g_qn[qtok];

    float m = -1e30f, l = 0.f;
    float acc[16];
#pragma unroll
    for (int j = 0; j < 16; j++) acc[j] = 0.f;

    for (int ct = 0; ct < 4; ct++) {
        const int cbase = ct * 128;
        __syncthreads();   // previous tile's PV fully drained before overwrite
        for (int idx = tid; idx < 128 * K_PAD; idx += 512) {
            int cc = idx / K_PAD, d = idx - cc * K_PAD;
            kt[idx] = (d < DK) ? g_k[((size_t)b * NC + cbase + cc) * DK + d] : 0.f;
        }
        for (int idx = tid; idx < 128 * V_PAD; idx += 512) {
            int cc = idx >> 6, d = idx & 63;
            vt[idx] = (d < DV) ? g_v[((size_t)b * NC + cbase + cc) * DV + d] : 0.f;
        }
        if (tid < 128) {
            kn_s[tid] = g_kn[(size_t)b * NC + cbase + tid];
            pb_s[tid] = pos_bias[cbase + tid];
        }
        __syncthreads();

        // --- scores: each thread 32 scores of row r ---
        float lmax = -1e30f;
        for (int i = 0; i < 32; i++) {
            int c = c0 + 4 * i;
            const float4* kp = (const float4*)(kt + c * K_PAD);
            float a0 = 0.f, a1 = 0.f;
#pragma unroll
            for (int kk = 0; kk < 15; kk++) {
                float4 k4 = kp[kk];
                a0 = fmaf(qreg[kk].x, k4.x, a0);
                a1 = fmaf(qreg[kk].y, k4.y, a1);
                a0 = fmaf(qreg[kk].z, k4.z, a0);
                a1 = fmaf(qreg[kk].w, k4.w, a1);
            }
            float sc = (a0 + a1) / fmaxf(qn * kn_s[c], EPSV) + pb_s[c];
            s_s[r * S_PAD + c] = sc;
            lmax = fmaxf(lmax, sc);
        }

        // --- online softmax (4-lane group per row) ---
        lmax = fmaxf(lmax, __shfl_xor_sync(0xffffffffu, lmax, 1));
        lmax = fmaxf(lmax, __shfl_xor_sync(0xffffffffu, lmax, 2));
        float newm = fmaxf(m, lmax);
        float corr = __expf(m - newm);
        float lsum = 0.f;
        for (int i = 0; i < 32; i++) {
            int c = c0 + 4 * i;
            float p = __expf(s_s[r * S_PAD + c] - newm);
            s_s[r * S_PAD + c] = p;
            lsum += p;
        }
        lsum += __shfl_xor_sync(0xffffffffu, lsum, 1);
        lsum += __shfl_xor_sync(0xffffffffu, lsum, 2);
        l = l * corr + lsum;
        m = newm;
#pragma unroll
        for (int j = 0; j < 16; j++) acc[j] *= corr;
        __syncwarp();   // p values of row r come from lanes of this warp only

        // --- P @ V : thread owns dv chunk c0*16..c0*16+15 of row r ---
        const float* vbase = vt + c0 * 16;
        for (int c = 0; c < 128; c++) {
            float p = s_s[r * S_PAD + c];
            const float4* vp = (const float4*)(vbase + c * V_PAD);
            float4 v0 = vp[0], v1 = vp[1], v2 = vp[2], v3 = vp[3];
            acc[0]  = fmaf(p, v0.x, acc[0]);
            acc[1]  = fmaf(p, v0.y, acc[1]);
            acc[2]  = fmaf(p, v0.z, acc[2]);
            acc[3]  = fmaf(p, v0.w, acc[3]);
            acc[4]  = fmaf(p, v1.x, acc[4]);
            acc[5]  = fmaf(p, v1.y, acc[5]);
            acc[6]  = fmaf(p, v1.z, acc[6]);
            acc[7]  = fmaf(p, v1.w, acc[7]);
            acc[8]  = fmaf(p, v2.x, acc[8]);
            acc[9]  = fmaf(p, v2.y, acc[9]);
            acc[10] = fmaf(p, v2.z, acc[10]);
            acc[11] = fmaf(p, v2.w, acc[11]);
            acc[12] = fmaf(p, v3.x, acc[12]);
            acc[13] = fmaf(p, v3.y, acc[13]);
            acc[14] = fmaf(p, v3.z, acc[14]);
            acc[15] = fmaf(p, v3.w, acc[15]);
        }
    }

    // --- epilogue: out[b,t,:] = ao @ R_w^T + R_b ---
    __syncthreads();                       // all PV reads of s_s done
    float* ao = s_s;                       // reuse as [128][68]
    {
        const float invl = 1.f / l;
        const int d0 = c0 * 16;
#pragma unroll
        for (int j = 0; j < 16; j++) {
            int d = d0 + j;
            ao[r * R_PAD + d] = (d < DV) ? acc[j] * invl : 0.f;
        }
    }
    for (int idx = tid; idx < 256 * R_PAD; idx += 512) {
        int e = idx / R_PAD, d = idx - e * R_PAD;
        Rs[idx] = (d < DV) ? R_w[e * DV + d] : 0.f;
    }
    __syncthreads();

    const int e  = tid & 255;
    const int rh = tid >> 8;
    const float bj = R_b[e];
    const float4* Re = (const float4*)(Rs + e * R_PAD);
    for (int rg = 0; rg < 8; rg++) {
        int r0 = rh * 64 + rg * 8;
        float a[8];
#pragma unroll
        for (int rr = 0; rr < 8; rr++) a[rr] = bj;
        for (int kk = 0; kk < 15; kk++) {
            float4 w4 = Re[kk];
#pragma unroll
            for (int rr = 0; rr < 8; rr++) {
                float4 a4 = *(const float4*)(ao + (r0 + rr) * R_PAD + kk * 4);
                a[rr] = fmaf(a4.x, w4.x, a[rr]);
                a[rr] = fmaf(a4.y, w4.y, a[rr]);
                a[rr] = fmaf(a4.z, w4.z, a[rr]);
                a[rr] = fmaf(a4.w, w4.w, a[rr]);
            }
        }
#pragma unroll
        for (int rr = 0; rr < 8; rr++)
            out[((size_t)b * NT + tq0 + r0 + rr) * EMB + e] = a[rr];
    }
}

// ---------------------------------------------------------------------------
// launch
// ---------------------------------------------------------------------------
extern "C" void kernel_launch(void* const* d_in, const int* in_sizes, int n_in,
                              void* d_out, int out_size)
{
    const int*   titems   = (const int*)  d_in[0];
    const int*   citems   = (const int*)  d_in[1];
    const float* tvec     = (const float*)d_in[2];
    const float* cvec     = (const float*)d_in[3];
    const float* At_w     = (const float*)d_in[4];
    const float* At_b     = (const float*)d_in[5];
    const float* Ac_w     = (const float*)d_in[6];
    const float* Ac_b     = (const float*)d_in[7];
    const float* Bc_w     = (const float*)d_in[8];
    const float* Bc_b     = (const float*)d_in[9];
    const float* pos_bias = (const float*)d_in[10];
    const float* R_w      = (const float*)d_in[11];
    const float* R_b      = (const float*)d_in[12];
    float* out = (float*)d_out;

    const int smem_q  = (256 * 64 + 32 * 256 + 64) * 4;    // 98560
    const int smem_kv = (256 * 128 + 16 * 256 + 32) * 4;   // 147584
    const int smem_at = (128 * S_PAD + 17408 + 256) * 4;   // 138240

    cudaFuncSetAttribute(proj_q_kernel,  cudaFuncAttributeMaxDynamicSharedMemorySize, smem_q);
    cudaFuncSetAttribute(proj_kv_kernel, cudaFuncAttributeMaxDynamicSharedMemorySize, smem_kv);
    cudaFuncSetAttribute(attn_kernel,    cudaFuncAttributeMaxDynamicSharedMemorySize, smem_at);

    proj_q_kernel <<< NTOK / 32,  dim3(64, 4),  smem_q  >>>(titems, tvec, At_w, At_b);
    proj_kv_kernel<<< NCTOK / 16, dim3(128, 2), smem_kv >>>(citems, cvec, Ac_w, Ac_b, Bc_w, Bc_b);
    attn_kernel   <<< dim3(NT / 128, BATCH), 512, smem_at >>>(pos_bias, R_w, R_b, out);
}

// round 2
// speedup vs baseline: 2.7586x; 2.7586x over previous
#include <cuda_runtime.h>
#include <math.h>

#define BATCH   128
#define NT      512
#define NC      512
#define EMB     256
#define DK      60
#define DV      60
#define NTOK    (BATCH * NT)
#define NCTOK   (BATCH * NC)
#define EPSV    1e-6f

__device__ float g_q [NTOK  * DK];
__device__ float g_k [NCTOK * DK];
__device__ float g_v [NCTOK * DV];
__device__ float g_qn[NTOK];
__device__ float g_kn[NCTOK];

// ---------------------------------------------------------------------------
// proj_q: 128 tokens/block, 512 threads. C[128t][64j] = E[128][256] x Wt
// thread tile 4t x 4j; embT[k][t] and Wt[k][j] transposed in smem.
// ---------------------------------------------------------------------------
__global__ void __launch_bounds__(512) proj_q_kernel(
    const int* __restrict__ items, const float* __restrict__ tvec,
    const float* __restrict__ W, const float* __restrict__ bias)
{
    extern __shared__ float sm[];
    float* Wt   = sm;               // [256][64]
    float* embT = sm + 256 * 64;    // [256][132]
    int*   its  = (int*)(embT + 256 * 132);

    const int tid = threadIdx.x;
    const int tx  = tid & 15;       // j4 = tx*4
    const int ty  = tid >> 4;       // t4 = ty*4 (0..31)
    const int base = blockIdx.x * 128;

    if (tid < 128) its[tid] = items[base + tid];
    for (int idx = tid; idx < 64 * 64; idx += 512) {
        int j = idx & 63, kq = idx >> 6;
        float4 w = make_float4(0.f, 0.f, 0.f, 0.f);
        if (j < DK) w = *(const float4*)(W + j * EMB + kq * 4);
        Wt[(kq * 4 + 0) * 64 + j] = w.x;
        Wt[(kq * 4 + 1) * 64 + j] = w.y;
        Wt[(kq * 4 + 2) * 64 + j] = w.z;
        Wt[(kq * 4 + 3) * 64 + j] = w.w;
    }
    __syncthreads();
    for (int idx = tid; idx < 64 * 128; idx += 512) {
        int t = idx & 127, kq = idx >> 7;
        float4 e = *(const float4*)(tvec + (size_t)its[t] * EMB + kq * 4);
        embT[(kq * 4 + 0) * 132 + t] = e.x;
        embT[(kq * 4 + 1) * 132 + t] = e.y;
        embT[(kq * 4 + 2) * 132 + t] = e.z;
        embT[(kq * 4 + 3) * 132 + t] = e.w;
    }
    __syncthreads();

    float acc[4][4];
#pragma unroll
    for (int i = 0; i < 4; i++)
#pragma unroll
        for (int j = 0; j < 4; j++) acc[i][j] = 0.f;

#pragma unroll 4
    for (int k = 0; k < 256; k++) {
        float4 e4 = *(const float4*)(embT + k * 132 + ty * 4);
        float4 w4 = *(const float4*)(Wt   + k * 64  + tx * 4);
        float ev[4] = {e4.x, e4.y, e4.z, e4.w};
        float wv[4] = {w4.x, w4.y, w4.z, w4.w};
#pragma unroll
        for (int i = 0; i < 4; i++)
#pragma unroll
            for (int j = 0; j < 4; j++)
                acc[i][j] = fmaf(ev[i], wv[j], acc[i][j]);
    }

    float bj[4];
#pragma unroll
    for (int j = 0; j < 4; j++) {
        int jj = tx * 4 + j;
        bj[j] = (jj < DK) ? bias[jj] : 0.f;
    }

#pragma unroll
    for (int i = 0; i < 4; i++) {
        int tok = base + ty * 4 + i;
        float v0 = acc[i][0] + bj[0], v1 = acc[i][1] + bj[1];
        float v2 = acc[i][2] + bj[2], v3 = acc[i][3] + bj[3];
        if (tx < 15)
            *(float4*)(g_q + (size_t)tok * DK + tx * 4) = make_float4(v0, v1, v2, v3);
        float sq = (tx < 15) ? (v0*v0 + v1*v1 + v2*v2 + v3*v3) : 0.f;
#pragma unroll
        for (int o = 8; o; o >>= 1) sq += __shfl_xor_sync(0xffffffffu, sq, o);
        if (tx == 0) g_qn[tok] = sqrtf(sq);
    }
}

// ---------------------------------------------------------------------------
// proj_kv: 64 tokens/block, 512 threads. 128 j-cols: [0,60)=k, [64,124)=v
// ---------------------------------------------------------------------------
__global__ void __launch_bounds__(512) proj_kv_kernel(
    const int* __restrict__ items, const float* __restrict__ cvec,
    const float* __restrict__ Wk, const float* __restrict__ bk,
    const float* __restrict__ Wv, const float* __restrict__ bv)
{
    extern __shared__ float sm[];
    float* Wt   = sm;               // [256][128]
    float* embT = sm + 256 * 128;   // [256][68]
    int*   its  = (int*)(embT + 256 * 68);

    const int tid = threadIdx.x;
    const int tx  = tid & 31;       // j4 = tx*4
    const int ty  = tid >> 5;       // t4 = ty*4 (0..15)
    const int base = blockIdx.x * 64;

    if (tid < 64) its[tid] = items[base + tid];
    for (int idx = tid; idx < 64 * 128; idx += 512) {
        int j = idx & 127, kq = idx >> 7;
        float4 w = make_float4(0.f, 0.f, 0.f, 0.f);
        if (j < DK)                      w = *(const float4*)(Wk + j * EMB + kq * 4);
        else if (j >= 64 && j < 64 + DV) w = *(const float4*)(Wv + (j - 64) * EMB + kq * 4);
        Wt[(kq * 4 + 0) * 128 + j] = w.x;
        Wt[(kq * 4 + 1) * 128 + j] = w.y;
        Wt[(kq * 4 + 2) * 128 + j] = w.z;
        Wt[(kq * 4 + 3) * 128 + j] = w.w;
    }
    __syncthreads();
    for (int idx = tid; idx < 64 * 64; idx += 512) {
        int t = idx & 63, kq = idx >> 6;
        float4 e = *(const float4*)(cvec + (size_t)its[t] * EMB + kq * 4);
        embT[(kq * 4 + 0) * 68 + t] = e.x;
        embT[(kq * 4 + 1) * 68 + t] = e.y;
        embT[(kq * 4 + 2) * 68 + t] = e.z;
        embT[(kq * 4 + 3) * 68 + t] = e.w;
    }
    __syncthreads();

    float acc[4][4];
#pragma unroll
    for (int i = 0; i < 4; i++)
#pragma unroll
        for (int j = 0; j < 4; j++) acc[i][j] = 0.f;

#pragma unroll 4
    for (int k = 0; k < 256; k++) {
        float4 e4 = *(const float4*)(embT + k * 68  + ty * 4);
        float4 w4 = *(const float4*)(Wt   + k * 128 + tx * 4);
        float ev[4] = {e4.x, e4.y, e4.z, e4.w};
        float wv[4] = {w4.x, w4.y, w4.z, w4.w};
#pragma unroll
        for (int i = 0; i < 4; i++)
#pragma unroll
            for (int j = 0; j < 4; j++)
                acc[i][j] = fmaf(ev[i], wv[j], acc[i][j]);
    }

    float bj[4];
#pragma unroll
    for (int j = 0; j < 4; j++) {
        int jj = tx * 4 + j;
        float b = 0.f;
        if (jj < DK) b = bk[jj];
        else if (jj >= 64 && jj < 64 + DV) b = bv[jj - 64];
        bj[j] = b;
    }

#pragma unroll
    for (int i = 0; i < 4; i++) {
        int tok = base + ty * 4 + i;
        float v0 = acc[i][0] + bj[0], v1 = acc[i][1] + bj[1];
        float v2 = acc[i][2] + bj[2], v3 = acc[i][3] + bj[3];
        if (tx < 15)
            *(float4*)(g_k + (size_t)tok * DK + tx * 4) = make_float4(v0, v1, v2, v3);
        else if (tx >= 16 && tx < 31)
            *(float4*)(g_v + (size_t)tok * DV + (tx - 16) * 4) = make_float4(v0, v1, v2, v3);
        float sq = (tx < 15) ? (v0*v0 + v1*v1 + v2*v2 + v3*v3) : 0.f;
#pragma unroll
        for (int o = 16; o; o >>= 1) sq += __shfl_xor_sync(0xffffffffu, sq, o);
        if (tx == 0) g_kn[tok] = sqrtf(sq);
    }
}

// ---------------------------------------------------------------------------
// attn: 128 q-rows/block x 512 ctx (4 tiles of 128), 512 threads, fused
//       cosine scores + online softmax + PV + output projection.
// smem (floats): Qt[64*132] | KV{KtT[64*132]+Vs[128*64]}/Rt[60*260]
//                | Pt[128*132]/AOt | m_s,l_s,corr_s[128 each]
// ---------------------------------------------------------------------------
#define QT_P 132
#define PT_P 132
#define RT_P 260

__global__ void __launch_bounds__(512) attn_kernel(
    const float* __restrict__ pos_bias,
    const float* __restrict__ R_w, const float* __restrict__ R_b,
    float* __restrict__ out)
{
    extern __shared__ float sm[];
    float* Qt   = sm;                       // [60][132]
    float* KtT  = sm + 64 * QT_P;           // [60][132]
    float* Vs   = KtT + 64 * QT_P;          // [128][64]
    float* Rt   = KtT;                      // [60][260] (epilogue reuse)
    float* Pt   = sm + 64 * QT_P + 16640;   // [128][132]
    float* AOt  = Pt;                       // [64][132] (epilogue reuse)
    float* m_s  = Pt + 128 * PT_P;          // [128]
    float* l_s  = m_s + 128;                // [128]
    float* corr_s = l_s + 128;              // [128]

    const int b   = blockIdx.y;
    const int tq0 = blockIdx.x * 128;
    const int tid = threadIdx.x;
    const int tx  = tid & 31;               // score: c4 = tx*4
    const int ty  = tid >> 5;               // rows ty*8..ty*8+7
    const int txl = tx & 15;                // PV/epi: dv4 = txl*4
    const int txh = tx >> 4;                // PV: row half
    const int r0pv = ty * 8 + txh * 4;      // PV rows r0pv..r0pv+3

    // stage Qt (transposed) + init stats
    for (int idx = tid; idx < 15 * 128; idx += 512) {
        int t = idx & 127, kq = idx >> 7;
        float4 q4 = *(const float4*)(g_q + (size_t)(b * NT + tq0 + t) * DK + kq * 4);
        Qt[(kq * 4 + 0) * QT_P + t] = q4.x;
        Qt[(kq * 4 + 1) * QT_P + t] = q4.y;
        Qt[(kq * 4 + 2) * QT_P + t] = q4.z;
        Qt[(kq * 4 + 3) * QT_P + t] = q4.w;
    }
    if (tid < 128) { m_s[tid] = -1e30f; l_s[tid] = 0.f; }

    float qn_r[8];
#pragma unroll
    for (int i = 0; i < 8; i++) qn_r[i] = g_qn[b * NT + tq0 + ty * 8 + i];

    float oa[4][4];
#pragma unroll
    for (int i = 0; i < 4; i++)
#pragma unroll
        for (int j = 0; j < 4; j++) oa[i][j] = 0.f;

    for (int ct = 0; ct < 4; ct++) {
        const int cbase = ct * 128;
        __syncthreads();
        for (int idx = tid; idx < 15 * 128; idx += 512) {
            int c = idx & 127, kq = idx >> 7;
            float4 k4 = *(const float4*)(g_k + (size_t)(b * NC + cbase + c) * DK + kq * 4);
            KtT[(kq * 4 + 0) * QT_P + c] = k4.x;
            KtT[(kq * 4 + 1) * QT_P + c] = k4.y;
            KtT[(kq * 4 + 2) * QT_P + c] = k4.z;
            KtT[(kq * 4 + 3) * QT_P + c] = k4.w;
        }
        for (int idx = tid; idx < 15 * 128; idx += 512) {
            int c = idx & 127, kq = idx >> 7;
            float4 v4 = *(const float4*)(g_v + (size_t)(b * NC + cbase + c) * DV + kq * 4);
            *(float4*)(Vs + c * 64 + kq * 4) = v4;
        }
        if (tid < 128) *(float4*)(Vs + tid * 64 + 60) = make_float4(0.f, 0.f, 0.f, 0.f);

        float kn_c[4], pb_c[4];
#pragma unroll
        for (int j = 0; j < 4; j++) {
            int c = tx * 4 + j;
            kn_c[j] = g_kn[b * NC + cbase + c];
            pb_c[j] = pos_bias[cbase + c];
        }
        __syncthreads();

        // ---- scores: 8 rows x 4 cols per thread ----
        float s[8][4];
#pragma unroll
        for (int i = 0; i < 8; i++)
#pragma unroll
            for (int j = 0; j < 4; j++) s[i][j] = 0.f;

#pragma unroll 4
        for (int k = 0; k < 60; k++) {
            float4 a0 = *(const float4*)(Qt + k * QT_P + ty * 8);
            float4 a1 = *(const float4*)(Qt + k * QT_P + ty * 8 + 4);
            float4 b0 = *(const float4*)(KtT + k * QT_P + tx * 4);
            float av[8] = {a0.x, a0.y, a0.z, a0.w, a1.x, a1.y, a1.z, a1.w};
            float bv[4] = {b0.x, b0.y, b0.z, b0.w};
#pragma unroll
            for (int i = 0; i < 8; i++)
#pragma unroll
                for (int j = 0; j < 4; j++)
                    s[i][j] = fmaf(av[i], bv[j], s[i][j]);
        }

        // ---- post: cosine + bias, online softmax (one warp per 8 rows) ----
#pragma unroll
        for (int i = 0; i < 8; i++) {
            int r = ty * 8 + i;
#pragma unroll
            for (int j = 0; j < 4; j++)
                s[i][j] = __fdividef(s[i][j], fmaxf(qn_r[i] * kn_c[j], EPSV)) + pb_c[j];
            float rm = fmaxf(fmaxf(s[i][0], s[i][1]), fmaxf(s[i][2], s[i][3]));
#pragma unroll
            for (int o = 16; o; o >>= 1) rm = fmaxf(rm, __shfl_xor_sync(0xffffffffu, rm, o));
            float mold = m_s[r];
            float newm = fmaxf(mold, rm);
            float corr = __expf(mold - newm);
            float sum = 0.f;
#pragma unroll
            for (int j = 0; j < 4; j++) {
                float p = __expf(s[i][j] - newm);
                s[i][j] = p;
                sum += p;
            }
#pragma unroll
            for (int o = 16; o; o >>= 1) sum += __shfl_xor_sync(0xffffffffu, sum, o);
            if (tx == 0) {
                m_s[r] = newm;
                l_s[r] = l_s[r] * corr + sum;
                corr_s[r] = corr;
            }
        }

        // ---- write P transposed (XOR-swizzled on c>>3) ----
#pragma unroll
        for (int j = 0; j < 4; j++) {
            int c = tx * 4 + j;
            int sw = ((c >> 3) & 7) << 2;
            *(float4*)(Pt + c * PT_P + ((ty * 8) ^ sw)) =
                make_float4(s[0][j], s[1][j], s[2][j], s[3][j]);
            *(float4*)(Pt + c * PT_P + ((ty * 8 + 4) ^ sw)) =
                make_float4(s[4][j], s[5][j], s[6][j], s[7][j]);
        }
        __syncthreads();

        // ---- PV: 4 rows x 4 dv per thread ----
        {
            float c0 = corr_s[r0pv + 0], c1 = corr_s[r0pv + 1];
            float c2 = corr_s[r0pv + 2], c3 = corr_s[r0pv + 3];
#pragma unroll
            for (int j = 0; j < 4; j++) {
                oa[0][j] *= c0; oa[1][j] *= c1; oa[2][j] *= c2; oa[3][j] *= c3;
            }
        }
#pragma unroll 4
        for (int c = 0; c < 128; c++) {
            int sw = ((c >> 3) & 7) << 2;
            float4 p4 = *(const float4*)(Pt + c * PT_P + (r0pv ^ sw));
            float4 v4 = *(const float4*)(Vs + c * 64 + txl * 4);
            float pv[4] = {p4.x, p4.y, p4.z, p4.w};
            float vv[4] = {v4.x, v4.y, v4.z, v4.w};
#pragma unroll
            for (int i = 0; i < 4; i++)
#pragma unroll
                for (int j = 0; j < 4; j++)
                    oa[i][j] = fmaf(pv[i], vv[j], oa[i][j]);
        }
    }

    // ---- epilogue: AOt (normalized, transposed) + Rt stage ----
    __syncthreads();
#pragma unroll
    for (int i = 0; i < 4; i++) {
        float invl = __fdividef(1.f, l_s[r0pv + i]);
#pragma unroll
        for (int j = 0; j < 4; j++)
            AOt[(txl * 4 + j) * PT_P + r0pv + i] = oa[i][j] * invl;
    }
    for (int idx = tid; idx < 15 * 256; idx += 512) {
        int e = idx & 255, kq = idx >> 8;
        float4 w = *(const float4*)(R_w + e * DV + kq * 4);
        Rt[(kq * 4 + 0) * RT_P + e] = w.x;
        Rt[(kq * 4 + 1) * RT_P + e] = w.y;
        Rt[(kq * 4 + 2) * RT_P + e] = w.z;
        Rt[(kq * 4 + 3) * RT_P + e] = w.w;
    }
    __syncthreads();

    // ---- out[128][256] = AO[128][60] @ Rt : 8 rows x 8 e per thread ----
    {
        float o2[8][8];
#pragma unroll
        for (int i = 0; i < 8; i++)
#pragma unroll
            for (int j = 0; j < 8; j++) o2[i][j] = 0.f;
        const int e0 = tx * 8;
#pragma unroll 4
        for (int k = 0; k < 60; k++) {
            float4 a0 = *(const float4*)(AOt + k * PT_P + ty * 8);
            float4 a1 = *(const float4*)(AOt + k * PT_P + ty * 8 + 4);
            float4 w0 = *(const float4*)(Rt + k * RT_P + e0);
            float4 w1 = *(const float4*)(Rt + k * RT_P + e0 + 4);
            float av[8] = {a0.x, a0.y, a0.z, a0.w, a1.x, a1.y, a1.z, a1.w};
            float wv[8] = {w0.x, w0.y, w0.z, w0.w, w1.x, w1.y, w1.z, w1.w};
#pragma unroll
            for (int i = 0; i < 8; i++)
#pragma unroll
                for (int j = 0; j < 8; j++)
                    o2[i][j] = fmaf(av[i], wv[j], o2[i][j]);
        }
        float4 rb0 = *(const float4*)(R_b + e0);
        float4 rb1 = *(const float4*)(R_b + e0 + 4);
#pragma unroll
        for (int i = 0; i < 8; i++) {
            size_t o = (size_t)(b * NT + tq0 + ty * 8 + i) * EMB + e0;
            *(float4*)(out + o) = make_float4(o2[i][0] + rb0.x, o2[i][1] + rb0.y,
                                              o2[i][2] + rb0.z, o2[i][3] + rb0.w);
            *(float4*)(out + o + 4) = make_float4(o2[i][4] + rb1.x, o2[i][5] + rb1.y,
                                                  o2[i][6] + rb1.z, o2[i][7] + rb1.w);
        }
    }
}

// ---------------------------------------------------------------------------
extern "C" void kernel_launch(void* const* d_in, const int* in_sizes, int n_in,
                              void* d_out, int out_size)
{
    const int*   titems   = (const int*)  d_in[0];
    const int*   citems   = (const int*)  d_in[1];
    const float* tvec     = (const float*)d_in[2];
    const float* cvec     = (const float*)d_in[3];
    const float* At_w     = (const float*)d_in[4];
    const float* At_b     = (const float*)d_in[5];
    const float* Ac_w     = (const float*)d_in[6];
    const float* Ac_b     = (const float*)d_in[7];
    const float* Bc_w     = (const float*)d_in[8];
    const float* Bc_b     = (const float*)d_in[9];
    const float* pos_bias = (const float*)d_in[10];
    const float* R_w      = (const float*)d_in[11];
    const float* R_b      = (const float*)d_in[12];
    float* out = (float*)d_out;

    const int smem_q  = (256 * 64 + 256 * 132) * 4 + 128 * 4;           // 201216
    const int smem_kv = (256 * 128 + 256 * 68) * 4 + 64 * 4;            // 200960
    const int smem_at = (64 * QT_P + 16640 + 128 * PT_P + 384) * 4;     // 169472

    cudaFuncSetAttribute(proj_q_kernel,  cudaFuncAttributeMaxDynamicSharedMemorySize, smem_q);
    cudaFuncSetAttribute(proj_kv_kernel, cudaFuncAttributeMaxDynamicSharedMemorySize, smem_kv);
    cudaFuncSetAttribute(attn_kernel,    cudaFuncAttributeMaxDynamicSharedMemorySize, smem_at);

    proj_q_kernel <<< NTOK / 128, 512, smem_q  >>>(titems, tvec, At_w, At_b);
    proj_kv_kernel<<< NCTOK / 64, 512, smem_kv >>>(citems, cvec, Ac_w, Ac_b, Bc_w, Bc_b);
    attn_kernel   <<< dim3(NT / 128, BATCH), 512, smem_at >>>(pos_bias, R_w, R_b, out);
}

// round 3
// speedup vs baseline: 2.9965x; 1.0862x over previous
#include <cuda_runtime.h>
#include <math.h>

#define BATCH   128
#define NT      512
#define NC      512
#define EMB     256
#define DK      60
#define DV      60
#define NTOK    (BATCH * NT)
#define NCTOK   (BATCH * NC)
#define EPSV    1e-6f

typedef unsigned long long u64;

// packed f32x2 helpers (Blackwell full-rate FMA path; exact fp32 per lane)
__device__ __forceinline__ u64 pack2(float x) {
    u64 r; asm("mov.b64 %0, {%1, %1};" : "=l"(r) : "f"(x)); return r;
}
__device__ __forceinline__ void ffma2(u64& d, u64 a, u64 b) {
    asm("fma.rn.f32x2 %0, %1, %2, %3;" : "=l"(d) : "l"(a), "l"(b), "l"(d));
}
__device__ __forceinline__ u64 mul2(u64 a, u64 b) {
    u64 r; asm("mul.rn.f32x2 %0, %1, %2;" : "=l"(r) : "l"(a), "l"(b)); return r;
}
__device__ __forceinline__ float2 unpack2(u64 v) {
    float2 f; asm("mov.b64 {%0, %1}, %2;" : "=f"(f.x), "=f"(f.y) : "l"(v)); return f;
}

__device__ float g_q [NTOK  * DK];
__device__ float g_k [NCTOK * DK];
__device__ float g_v [NCTOK * DV];
__device__ float g_qn[NTOK];
__device__ float g_kn[NCTOK];

// ---------------------------------------------------------------------------
// proj_q: 128 tokens/block, 512 threads. thread tile 4t x 4j (f32x2-packed)
// ---------------------------------------------------------------------------
__global__ void __launch_bounds__(512) proj_q_kernel(
    const int* __restrict__ items, const float* __restrict__ tvec,
    const float* __restrict__ W, const float* __restrict__ bias)
{
    extern __shared__ float sm[];
    float* Wt   = sm;               // [256][64]
    float* embT = sm + 256 * 64;    // [256][132]
    int*   its  = (int*)(embT + 256 * 132);

    const int tid = threadIdx.x;
    const int tx  = tid & 15;
    const int ty  = tid >> 4;
    const int base = blockIdx.x * 128;

    if (tid < 128) its[tid] = items[base + tid];
    for (int idx = tid; idx < 64 * 64; idx += 512) {
        int j = idx & 63, kq = idx >> 6;
        float4 w = make_float4(0.f, 0.f, 0.f, 0.f);
        if (j < DK) w = *(const float4*)(W + j * EMB + kq * 4);
        Wt[(kq * 4 + 0) * 64 + j] = w.x;
        Wt[(kq * 4 + 1) * 64 + j] = w.y;
        Wt[(kq * 4 + 2) * 64 + j] = w.z;
        Wt[(kq * 4 + 3) * 64 + j] = w.w;
    }
    __syncthreads();
    for (int idx = tid; idx < 64 * 128; idx += 512) {
        int t = idx & 127, kq = idx >> 7;
        float4 e = *(const float4*)(tvec + (size_t)its[t] * EMB + kq * 4);
        embT[(kq * 4 + 0) * 132 + t] = e.x;
        embT[(kq * 4 + 1) * 132 + t] = e.y;
        embT[(kq * 4 + 2) * 132 + t] = e.z;
        embT[(kq * 4 + 3) * 132 + t] = e.w;
    }
    __syncthreads();

    u64 acc2[4][2];
#pragma unroll
    for (int i = 0; i < 4; i++) { acc2[i][0] = 0ull; acc2[i][1] = 0ull; }

#pragma unroll 4
    for (int k = 0; k < 256; k++) {
        float4 e4 = *(const float4*)(embT + k * 132 + ty * 4);
        ulonglong2 w2 = *(const ulonglong2*)(Wt + k * 64 + tx * 4);
        float ev[4] = {e4.x, e4.y, e4.z, e4.w};
#pragma unroll
        for (int i = 0; i < 4; i++) {
            u64 a = pack2(ev[i]);
            ffma2(acc2[i][0], a, w2.x);
            ffma2(acc2[i][1], a, w2.y);
        }
    }

    float bj[4];
#pragma unroll
    for (int j = 0; j < 4; j++) {
        int jj = tx * 4 + j;
        bj[j] = (jj < DK) ? bias[jj] : 0.f;
    }

#pragma unroll
    for (int i = 0; i < 4; i++) {
        int tok = base + ty * 4 + i;
        float2 p0 = unpack2(acc2[i][0]), p1 = unpack2(acc2[i][1]);
        float v0 = p0.x + bj[0], v1 = p0.y + bj[1];
        float v2 = p1.x + bj[2], v3 = p1.y + bj[3];
        if (tx < 15)
            *(float4*)(g_q + (size_t)tok * DK + tx * 4) = make_float4(v0, v1, v2, v3);
        float sq = (tx < 15) ? (v0*v0 + v1*v1 + v2*v2 + v3*v3) : 0.f;
#pragma unroll
        for (int o = 8; o; o >>= 1) sq += __shfl_xor_sync(0xffffffffu, sq, o);
        if (tx == 0) g_qn[tok] = sqrtf(sq);
    }
}

// ---------------------------------------------------------------------------
// proj_kv: 64 tokens/block, 512 threads. 128 j-cols: [0,60)=k, [64,124)=v
// ---------------------------------------------------------------------------
__global__ void __launch_bounds__(512) proj_kv_kernel(
    const int* __restrict__ items, const float* __restrict__ cvec,
    const float* __restrict__ Wk, const float* __restrict__ bk,
    const float* __restrict__ Wv, const float* __restrict__ bv)
{
    extern __shared__ float sm[];
    float* Wt   = sm;               // [256][128]
    float* embT = sm + 256 * 128;   // [256][68]
    int*   its  = (int*)(embT + 256 * 68);

    const int tid = threadIdx.x;
    const int tx  = tid & 31;
    const int ty  = tid >> 5;
    const int base = blockIdx.x * 64;

    if (tid < 64) its[tid] = items[base + tid];
    for (int idx = tid; idx < 64 * 128; idx += 512) {
        int j = idx & 127, kq = idx >> 7;
        float4 w = make_float4(0.f, 0.f, 0.f, 0.f);
        if (j < DK)                      w = *(const float4*)(Wk + j * EMB + kq * 4);
        else if (j >= 64 && j < 64 + DV) w = *(const float4*)(Wv + (j - 64) * EMB + kq * 4);
        Wt[(kq * 4 + 0) * 128 + j] = w.x;
        Wt[(kq * 4 + 1) * 128 + j] = w.y;
        Wt[(kq * 4 + 2) * 128 + j] = w.z;
        Wt[(kq * 4 + 3) * 128 + j] = w.w;
    }
    __syncthreads();
    for (int idx = tid; idx < 64 * 64; idx += 512) {
        int t = idx & 63, kq = idx >> 6;
        float4 e = *(const float4*)(cvec + (size_t)its[t] * EMB + kq * 4);
        embT[(kq * 4 + 0) * 68 + t] = e.x;
        embT[(kq * 4 + 1) * 68 + t] = e.y;
        embT[(kq * 4 + 2) * 68 + t] = e.z;
        embT[(kq * 4 + 3) * 68 + t] = e.w;
    }
    __syncthreads();

    u64 acc2[4][2];
#pragma unroll
    for (int i = 0; i < 4; i++) { acc2[i][0] = 0ull; acc2[i][1] = 0ull; }

#pragma unroll 4
    for (int k = 0; k < 256; k++) {
        float4 e4 = *(const float4*)(embT + k * 68 + ty * 4);
        ulonglong2 w2 = *(const ulonglong2*)(Wt + k * 128 + tx * 4);
        float ev[4] = {e4.x, e4.y, e4.z, e4.w};
#pragma unroll
        for (int i = 0; i < 4; i++) {
            u64 a = pack2(ev[i]);
            ffma2(acc2[i][0], a, w2.x);
            ffma2(acc2[i][1], a, w2.y);
        }
    }

    float bj[4];
#pragma unroll
    for (int j = 0; j < 4; j++) {
        int jj = tx * 4 + j;
        float b = 0.f;
        if (jj < DK) b = bk[jj];
        else if (jj >= 64 && jj < 64 + DV) b = bv[jj - 64];
        bj[j] = b;
    }

#pragma unroll
    for (int i = 0; i < 4; i++) {
        int tok = base + ty * 4 + i;
        float2 p0 = unpack2(acc2[i][0]), p1 = unpack2(acc2[i][1]);
        float v0 = p0.x + bj[0], v1 = p0.y + bj[1];
        float v2 = p1.x + bj[2], v3 = p1.y + bj[3];
        if (tx < 15)
            *(float4*)(g_k + (size_t)tok * DK + tx * 4) = make_float4(v0, v1, v2, v3);
        else if (tx >= 16 && tx < 31)
            *(float4*)(g_v + (size_t)tok * DV + (tx - 16) * 4) = make_float4(v0, v1, v2, v3);
        float sq = (tx < 15) ? (v0*v0 + v1*v1 + v2*v2 + v3*v3) : 0.f;
#pragma unroll
        for (int o = 16; o; o >>= 1) sq += __shfl_xor_sync(0xffffffffu, sq, o);
        if (tx == 0) g_kn[tok] = sqrtf(sq);
    }
}

// ---------------------------------------------------------------------------
// attn: 128 q-rows/block x 512 ctx, 512 threads, fused; f32x2-packed loops
// ---------------------------------------------------------------------------
#define QT_P 132
#define PT_P 132
#define RT_P 260

__global__ void __launch_bounds__(512) attn_kernel(
    const float* __restrict__ pos_bias,
    const float* __restrict__ R_w, const float* __restrict__ R_b,
    float* __restrict__ out)
{
    extern __shared__ float sm[];
    float* Qt   = sm;                       // [60][132]
    float* KtT  = sm + 64 * QT_P;           // [60][132]
    float* Vs   = KtT + 64 * QT_P;          // [128][64]
    float* Rt   = KtT;                      // [60][260] (epilogue reuse)
    float* Pt   = sm + 64 * QT_P + 16640;   // [128][132]
    float* AOt  = Pt;                       // [64][132] (epilogue reuse)
    float* m_s  = Pt + 128 * PT_P;          // [128]
    float* l_s  = m_s + 128;                // [128]
    float* corr_s = l_s + 128;              // [128]

    const int b   = blockIdx.y;
    const int tq0 = blockIdx.x * 128;
    const int tid = threadIdx.x;
    const int tx  = tid & 31;
    const int ty  = tid >> 5;
    const int txl = tx & 15;
    const int txh = tx >> 4;
    const int r0pv = ty * 8 + txh * 4;

    for (int idx = tid; idx < 15 * 128; idx += 512) {
        int t = idx & 127, kq = idx >> 7;
        float4 q4 = *(const float4*)(g_q + (size_t)(b * NT + tq0 + t) * DK + kq * 4);
        Qt[(kq * 4 + 0) * QT_P + t] = q4.x;
        Qt[(kq * 4 + 1) * QT_P + t] = q4.y;
        Qt[(kq * 4 + 2) * QT_P + t] = q4.z;
        Qt[(kq * 4 + 3) * QT_P + t] = q4.w;
    }
    if (tid < 128) { m_s[tid] = -1e30f; l_s[tid] = 0.f; }

    float qn_r[8];
#pragma unroll
    for (int i = 0; i < 8; i++) qn_r[i] = g_qn[b * NT + tq0 + ty * 8 + i];

    u64 oa2[4][2];
#pragma unroll
    for (int i = 0; i < 4; i++) { oa2[i][0] = 0ull; oa2[i][1] = 0ull; }

    for (int ct = 0; ct < 4; ct++) {
        const int cbase = ct * 128;
        __syncthreads();
        for (int idx = tid; idx < 15 * 128; idx += 512) {
            int c = idx & 127, kq = idx >> 7;
            float4 k4 = *(const float4*)(g_k + (size_t)(b * NC + cbase + c) * DK + kq * 4);
            KtT[(kq * 4 + 0) * QT_P + c] = k4.x;
            KtT[(kq * 4 + 1) * QT_P + c] = k4.y;
            KtT[(kq * 4 + 2) * QT_P + c] = k4.z;
            KtT[(kq * 4 + 3) * QT_P + c] = k4.w;
        }
        for (int idx = tid; idx < 15 * 128; idx += 512) {
            int c = idx & 127, kq = idx >> 7;
            float4 v4 = *(const float4*)(g_v + (size_t)(b * NC + cbase + c) * DV + kq * 4);
            *(float4*)(Vs + c * 64 + kq * 4) = v4;
        }
        if (tid < 128) *(float4*)(Vs + tid * 64 + 60) = make_float4(0.f, 0.f, 0.f, 0.f);

        float kn_c[4], pb_c[4];
#pragma unroll
        for (int j = 0; j < 4; j++) {
            int c = tx * 4 + j;
            kn_c[j] = g_kn[b * NC + cbase + c];
            pb_c[j] = pos_bias[cbase + c];
        }
        __syncthreads();

        // ---- scores: 8 rows x 4 cols per thread (packed) ----
        u64 s2[8][2];
#pragma unroll
        for (int i = 0; i < 8; i++) { s2[i][0] = 0ull; s2[i][1] = 0ull; }

#pragma unroll 4
        for (int k = 0; k < 60; k++) {
            float4 a0 = *(const float4*)(Qt + k * QT_P + ty * 8);
            float4 a1 = *(const float4*)(Qt + k * QT_P + ty * 8 + 4);
            ulonglong2 b2 = *(const ulonglong2*)(KtT + k * QT_P + tx * 4);
            float av[8] = {a0.x, a0.y, a0.z, a0.w, a1.x, a1.y, a1.z, a1.w};
#pragma unroll
            for (int i = 0; i < 8; i++) {
                u64 a = pack2(av[i]);
                ffma2(s2[i][0], a, b2.x);
                ffma2(s2[i][1], a, b2.y);
            }
        }

        float s[8][4];
#pragma unroll
        for (int i = 0; i < 8; i++) {
            float2 p0 = unpack2(s2[i][0]), p1 = unpack2(s2[i][1]);
            s[i][0] = p0.x; s[i][1] = p0.y; s[i][2] = p1.x; s[i][3] = p1.y;
        }

        // ---- cosine + bias, online softmax (one warp per 8 rows) ----
#pragma unroll
        for (int i = 0; i < 8; i++) {
            int r = ty * 8 + i;
#pragma unroll
            for (int j = 0; j < 4; j++)
                s[i][j] = __fdividef(s[i][j], fmaxf(qn_r[i] * kn_c[j], EPSV)) + pb_c[j];
            float rm = fmaxf(fmaxf(s[i][0], s[i][1]), fmaxf(s[i][2], s[i][3]));
#pragma unroll
            for (int o = 16; o; o >>= 1) rm = fmaxf(rm, __shfl_xor_sync(0xffffffffu, rm, o));
            float mold = m_s[r];
            float newm = fmaxf(mold, rm);
            float corr = __expf(mold - newm);
            float sum = 0.f;
#pragma unroll
            for (int j = 0; j < 4; j++) {
                float p = __expf(s[i][j] - newm);
                s[i][j] = p;
                sum += p;
            }
#pragma unroll
            for (int o = 16; o; o >>= 1) sum += __shfl_xor_sync(0xffffffffu, sum, o);
            if (tx == 0) {
                m_s[r] = newm;
                l_s[r] = l_s[r] * corr + sum;
                corr_s[r] = corr;
            }
        }

        // ---- write P transposed (XOR-swizzled on c>>3) ----
#pragma unroll
        for (int j = 0; j < 4; j++) {
            int c = tx * 4 + j;
            int sw = ((c >> 3) & 7) << 2;
            *(float4*)(Pt + c * PT_P + ((ty * 8) ^ sw)) =
                make_float4(s[0][j], s[1][j], s[2][j], s[3][j]);
            *(float4*)(Pt + c * PT_P + ((ty * 8 + 4) ^ sw)) =
                make_float4(s[4][j], s[5][j], s[6][j], s[7][j]);
        }
        __syncthreads();

        // ---- PV: 4 rows x 4 dv per thread (packed) ----
        {
#pragma unroll
            for (int i = 0; i < 4; i++) {
                u64 c2 = pack2(corr_s[r0pv + i]);
                oa2[i][0] = mul2(oa2[i][0], c2);
                oa2[i][1] = mul2(oa2[i][1], c2);
            }
        }
#pragma unroll 4
        for (int c = 0; c < 128; c++) {
            int sw = ((c >> 3) & 7) << 2;
            float4 p4 = *(const float4*)(Pt + c * PT_P + (r0pv ^ sw));
            ulonglong2 v2 = *(const ulonglong2*)(Vs + c * 64 + txl * 4);
            float pv[4] = {p4.x, p4.y, p4.z, p4.w};
#pragma unroll
            for (int i = 0; i < 4; i++) {
                u64 a = pack2(pv[i]);
                ffma2(oa2[i][0], a, v2.x);
                ffma2(oa2[i][1], a, v2.y);
            }
        }
    }

    // ---- epilogue: AOt (normalized, transposed) + Rt stage ----
    __syncthreads();
#pragma unroll
    for (int i = 0; i < 4; i++) {
        float invl = __fdividef(1.f, l_s[r0pv + i]);
        float2 p0 = unpack2(oa2[i][0]), p1 = unpack2(oa2[i][1]);
        AOt[(txl * 4 + 0) * PT_P + r0pv + i] = p0.x * invl;
        AOt[(txl * 4 + 1) * PT_P + r0pv + i] = p0.y * invl;
        AOt[(txl * 4 + 2) * PT_P + r0pv + i] = p1.x * invl;
        AOt[(txl * 4 + 3) * PT_P + r0pv + i] = p1.y * invl;
    }
    for (int idx = tid; idx < 15 * 256; idx += 512) {
        int e = idx & 255, kq = idx >> 8;
        float4 w = *(const float4*)(R_w + e * DV + kq * 4);
        Rt[(kq * 4 + 0) * RT_P + e] = w.x;
        Rt[(kq * 4 + 1) * RT_P + e] = w.y;
        Rt[(kq * 4 + 2) * RT_P + e] = w.z;
        Rt[(kq * 4 + 3) * RT_P + e] = w.w;
    }
    __syncthreads();

    // ---- out[128][256] = AO[128][60] @ Rt : 8 rows x 8 e per thread (packed)
    {
        u64 o22[8][4];
#pragma unroll
        for (int i = 0; i < 8; i++)
#pragma unroll
            for (int j = 0; j < 4; j++) o22[i][j] = 0ull;
        const int e0 = tx * 8;
#pragma unroll 4
        for (int k = 0; k < 60; k++) {
            float4 a0 = *(const float4*)(AOt + k * PT_P + ty * 8);
            float4 a1 = *(const float4*)(AOt + k * PT_P + ty * 8 + 4);
            ulonglong2 w0 = *(const ulonglong2*)(Rt + k * RT_P + e0);
            ulonglong2 w1 = *(const ulonglong2*)(Rt + k * RT_P + e0 + 4);
            float av[8] = {a0.x, a0.y, a0.z, a0.w, a1.x, a1.y, a1.z, a1.w};
#pragma unroll
            for (int i = 0; i < 8; i++) {
                u64 a = pack2(av[i]);
                ffma2(o22[i][0], a, w0.x);
                ffma2(o22[i][1], a, w0.y);
                ffma2(o22[i][2], a, w1.x);
                ffma2(o22[i][3], a, w1.y);
            }
        }
        float4 rb0 = *(const float4*)(R_b + e0);
        float4 rb1 = *(const float4*)(R_b + e0 + 4);
#pragma unroll
        for (int i = 0; i < 8; i++) {
            size_t o = (size_t)(b * NT + tq0 + ty * 8 + i) * EMB + e0;
            float2 q0 = unpack2(o22[i][0]), q1 = unpack2(o22[i][1]);
            float2 q2 = unpack2(o22[i][2]), q3 = unpack2(o22[i][3]);
            *(float4*)(out + o) = make_float4(q0.x + rb0.x, q0.y + rb0.y,
                                              q1.x + rb0.z, q1.y + rb0.w);
            *(float4*)(out + o + 4) = make_float4(q2.x + rb1.x, q2.y + rb1.y,
                                                  q3.x + rb1.z, q3.y + rb1.w);
        }
    }
}

// ---------------------------------------------------------------------------
extern "C" void kernel_launch(void* const* d_in, const int* in_sizes, int n_in,
                              void* d_out, int out_size)
{
    const int*   titems   = (const int*)  d_in[0];
    const int*   citems   = (const int*)  d_in[1];
    const float* tvec     = (const float*)d_in[2];
    const float* cvec     = (const float*)d_in[3];
    const float* At_w     = (const float*)d_in[4];
    const float* At_b     = (const float*)d_in[5];
    const float* Ac_w     = (const float*)d_in[6];
    const float* Ac_b     = (const float*)d_in[7];
    const float* Bc_w     = (const float*)d_in[8];
    const float* Bc_b     = (const float*)d_in[9];
    const float* pos_bias = (const float*)d_in[10];
    const float* R_w      = (const float*)d_in[11];
    const float* R_b      = (const float*)d_in[12];
    float* out = (float*)d_out;

    const int smem_q  = (256 * 64 + 256 * 132) * 4 + 128 * 4;
    const int smem_kv = (256 * 128 + 256 * 68) * 4 + 64 * 4;
    const int smem_at = (64 * QT_P + 16640 + 128 * PT_P + 384) * 4;

    cudaFuncSetAttribute(proj_q_kernel,  cudaFuncAttributeMaxDynamicSharedMemorySize, smem_q);
    cudaFuncSetAttribute(proj_kv_kernel, cudaFuncAttributeMaxDynamicSharedMemorySize, smem_kv);
    cudaFuncSetAttribute(attn_kernel,    cudaFuncAttributeMaxDynamicSharedMemorySize, smem_at);

    proj_q_kernel <<< NTOK / 128, 512, smem_q  >>>(titems, tvec, At_w, At_b);
    proj_kv_kernel<<< NCTOK / 64, 512, smem_kv >>>(citems, cvec, Ac_w, Ac_b, Bc_w, Bc_b);
    attn_kernel   <<< dim3(NT / 128, BATCH), 512, smem_at >>>(pos_bias, R_w, R_b, out);
}

// round 4
// speedup vs baseline: 3.4929x; 1.1657x over previous
#include <cuda_runtime.h>
#include <math.h>

#define BATCH   128
#define NT      512
#define NC      512
#define EMB     256
#define DK      60
#define DV      60
#define NTOK    (BATCH * NT)
#define NCTOK   (BATCH * NC)
#define EPSV    1e-6f

typedef unsigned long long u64;

__device__ __forceinline__ u64 pack2(float x) {
    u64 r; asm("mov.b64 %0, {%1, %1};" : "=l"(r) : "f"(x)); return r;
}
__device__ __forceinline__ void ffma2(u64& d, u64 a, u64 b) {
    asm("fma.rn.f32x2 %0, %1, %2, %3;" : "=l"(d) : "l"(a), "l"(b), "l"(d));
}
__device__ __forceinline__ u64 mul2(u64 a, u64 b) {
    u64 r; asm("mul.rn.f32x2 %0, %1, %2;" : "=l"(r) : "l"(a), "l"(b)); return r;
}
__device__ __forceinline__ float2 unpack2(u64 v) {
    float2 f; asm("mov.b64 {%0, %1}, %2;" : "=f"(f.x), "=f"(f.y) : "l"(v)); return f;
}

__device__ float g_q [NTOK  * DK];
__device__ float g_k [NCTOK * DK];
__device__ float g_v [NCTOK * DV];
__device__ float g_qn[NTOK];
__device__ float g_kn[NCTOK];
__device__ float g_ao[NTOK * DV];

// ---------------------------------------------------------------------------
// proj_q: 256 tokens/block, 256 threads, thread tile 8t x 8j, k-chunked (64)
// smem 85KB -> 2 CTAs/SM. Staging overlaps with other CTA's compute.
// ---------------------------------------------------------------------------
__global__ void __launch_bounds__(256) proj_q_kernel(
    const int* __restrict__ items, const float* __restrict__ tvec,
    const float* __restrict__ W, const float* __restrict__ bias)
{
    extern __shared__ float sm[];
    int*   its  = (int*)sm;            // 256
    float* Wt   = sm + 256;            // [64][64]  chunk, swizzled
    float* embT = Wt + 64 * 64;        // [64][264] chunk, swizzled

    const int tid = threadIdx.x;
    const int tx  = tid & 7;           // j0 = tx*8
    const int ty  = tid >> 3;          // t0 = ty*8 (0..31)
    const int base = blockIdx.x * 256;

    its[tid] = items[base + tid];

    u64 acc[8][4];
#pragma unroll
    for (int i = 0; i < 8; i++)
#pragma unroll
        for (int j = 0; j < 4; j++) acc[i][j] = 0ull;

    for (int c0 = 0; c0 < 4; c0++) {
        __syncthreads();
        // stage Wt chunk: row-parallel coalesced LDG, swizzled STS
        for (int idx = tid; idx < 64 * 16; idx += 256) {
            int j = idx >> 4, l = idx & 15;
            float4 w = make_float4(0.f, 0.f, 0.f, 0.f);
            if (j < DK) w = *(const float4*)(W + j * EMB + c0 * 64 + l * 4);
            int js = j ^ ((l & 7) << 2);
            Wt[(4 * l + 0) * 64 + js] = w.x;
            Wt[(4 * l + 1) * 64 + js] = w.y;
            Wt[(4 * l + 2) * 64 + js] = w.z;
            Wt[(4 * l + 3) * 64 + js] = w.w;
        }
        // stage embT chunk (gather): 256 rows x 16 float4, coalesced per row
        for (int idx = tid; idx < 256 * 16; idx += 256) {
            int t = idx >> 4, l = idx & 15;
            float4 e = *(const float4*)(tvec + (size_t)its[t] * EMB + c0 * 64 + l * 4);
            int ts = t ^ ((l & 7) << 2);
            embT[(4 * l + 0) * 264 + ts] = e.x;
            embT[(4 * l + 1) * 264 + ts] = e.y;
            embT[(4 * l + 2) * 264 + ts] = e.z;
            embT[(4 * l + 3) * 264 + ts] = e.w;
        }
        __syncthreads();

#pragma unroll 4
        for (int kc = 0; kc < 64; kc++) {
            int sw = ((kc >> 2) & 7) << 2;
            float4 a0 = *(const float4*)(embT + kc * 264 + ((ty * 8) ^ sw));
            float4 a1 = *(const float4*)(embT + kc * 264 + ((ty * 8 + 4) ^ sw));
            ulonglong2 b0 = *(const ulonglong2*)(Wt + kc * 64 + ((tx * 8) ^ sw));
            ulonglong2 b1 = *(const ulonglong2*)(Wt + kc * 64 + ((tx * 8 + 4) ^ sw));
            float av[8] = {a0.x, a0.y, a0.z, a0.w, a1.x, a1.y, a1.z, a1.w};
#pragma unroll
            for (int i = 0; i < 8; i++) {
                u64 a = pack2(av[i]);
                ffma2(acc[i][0], a, b0.x);
                ffma2(acc[i][1], a, b0.y);
                ffma2(acc[i][2], a, b1.x);
                ffma2(acc[i][3], a, b1.y);
            }
        }
    }

    float bj[8];
#pragma unroll
    for (int j = 0; j < 8; j++) {
        int jj = tx * 8 + j;
        bj[j] = (jj < DK) ? bias[jj] : 0.f;
    }

#pragma unroll
    for (int i = 0; i < 8; i++) {
        int tok = base + ty * 8 + i;
        float v[8];
        float2 p;
        p = unpack2(acc[i][0]); v[0] = p.x + bj[0]; v[1] = p.y + bj[1];
        p = unpack2(acc[i][1]); v[2] = p.x + bj[2]; v[3] = p.y + bj[3];
        p = unpack2(acc[i][2]); v[4] = p.x + bj[4]; v[5] = p.y + bj[5];
        p = unpack2(acc[i][3]); v[6] = p.x + bj[6]; v[7] = p.y + bj[7];
        if (tx < 7) {
            *(float4*)(g_q + (size_t)tok * DK + tx * 8)     = make_float4(v[0], v[1], v[2], v[3]);
            *(float4*)(g_q + (size_t)tok * DK + tx * 8 + 4) = make_float4(v[4], v[5], v[6], v[7]);
        } else {
            *(float4*)(g_q + (size_t)tok * DK + 56) = make_float4(v[0], v[1], v[2], v[3]);
        }
        float sq = v[0]*v[0] + v[1]*v[1] + v[2]*v[2] + v[3]*v[3];
        if (tx < 7) sq += v[4]*v[4] + v[5]*v[5] + v[6]*v[6] + v[7]*v[7];
#pragma unroll
        for (int o = 4; o; o >>= 1) sq += __shfl_xor_sync(0xffffffffu, sq, o);
        if (tx == 0) g_qn[tok] = sqrtf(sq);
    }
}

// ---------------------------------------------------------------------------
// proj_kv: 128 tokens/block, 256 threads, 8t x 8j over 128 j (k | pad | v)
// smem 68KB -> 2-3 CTAs/SM.
// ---------------------------------------------------------------------------
__global__ void __launch_bounds__(256) proj_kv_kernel(
    const int* __restrict__ items, const float* __restrict__ cvec,
    const float* __restrict__ Wk, const float* __restrict__ bk,
    const float* __restrict__ Wv, const float* __restrict__ bv)
{
    extern __shared__ float sm[];
    int*   its  = (int*)sm;            // 128
    float* Wt   = sm + 128;            // [64][128] chunk, swizzled
    float* embT = Wt + 64 * 128;       // [64][136] chunk, swizzled

    const int tid = threadIdx.x;
    const int tx  = tid & 15;          // j0 = tx*8 (0..120)
    const int ty  = tid >> 4;          // t0 = ty*8 (0..15)
    const int base = blockIdx.x * 128;

    if (tid < 128) its[tid] = items[base + tid];

    u64 acc[8][4];
#pragma unroll
    for (int i = 0; i < 8; i++)
#pragma unroll
        for (int j = 0; j < 4; j++) acc[i][j] = 0ull;

    for (int c0 = 0; c0 < 4; c0++) {
        __syncthreads();
        for (int idx = tid; idx < 128 * 16; idx += 256) {
            int j = idx >> 4, l = idx & 15;
            float4 w = make_float4(0.f, 0.f, 0.f, 0.f);
            if (j < DK)                      w = *(const float4*)(Wk + j * EMB + c0 * 64 + l * 4);
            else if (j >= 64 && j < 64 + DV) w = *(const float4*)(Wv + (j - 64) * EMB + c0 * 64 + l * 4);
            int js = j ^ ((l & 7) << 2);
            Wt[(4 * l + 0) * 128 + js] = w.x;
            Wt[(4 * l + 1) * 128 + js] = w.y;
            Wt[(4 * l + 2) * 128 + js] = w.z;
            Wt[(4 * l + 3) * 128 + js] = w.w;
        }
        for (int idx = tid; idx < 128 * 16; idx += 256) {
            int t = idx >> 4, l = idx & 15;
            float4 e = *(const float4*)(cvec + (size_t)its[t] * EMB + c0 * 64 + l * 4);
            int ts = t ^ ((l & 7) << 2);
            embT[(4 * l + 0) * 136 + ts] = e.x;
            embT[(4 * l + 1) * 136 + ts] = e.y;
            embT[(4 * l + 2) * 136 + ts] = e.z;
            embT[(4 * l + 3) * 136 + ts] = e.w;
        }
        __syncthreads();

#pragma unroll 4
        for (int kc = 0; kc < 64; kc++) {
            int sw = ((kc >> 2) & 7) << 2;
            float4 a0 = *(const float4*)(embT + kc * 136 + ((ty * 8) ^ sw));
            float4 a1 = *(const float4*)(embT + kc * 136 + ((ty * 8 + 4) ^ sw));
            ulonglong2 b0 = *(const ulonglong2*)(Wt + kc * 128 + ((tx * 8) ^ sw));
            ulonglong2 b1 = *(const ulonglong2*)(Wt + kc * 128 + ((tx * 8 + 4) ^ sw));
            float av[8] = {a0.x, a0.y, a0.z, a0.w, a1.x, a1.y, a1.z, a1.w};
#pragma unroll
            for (int i = 0; i < 8; i++) {
                u64 a = pack2(av[i]);
                ffma2(acc[i][0], a, b0.x);
                ffma2(acc[i][1], a, b0.y);
                ffma2(acc[i][2], a, b1.x);
                ffma2(acc[i][3], a, b1.y);
            }
        }
    }

    float bj[8];
#pragma unroll
    for (int j = 0; j < 8; j++) {
        int jj = tx * 8 + j;
        float bb = 0.f;
        if (jj < DK) bb = bk[jj];
        else if (jj >= 64 && jj < 64 + DV) bb = bv[jj - 64];
        bj[j] = bb;
    }

#pragma unroll
    for (int i = 0; i < 8; i++) {
        int tok = base + ty * 8 + i;
        float v[8];
        float2 p;
        p = unpack2(acc[i][0]); v[0] = p.x + bj[0]; v[1] = p.y + bj[1];
        p = unpack2(acc[i][1]); v[2] = p.x + bj[2]; v[3] = p.y + bj[3];
        p = unpack2(acc[i][2]); v[4] = p.x + bj[4]; v[5] = p.y + bj[5];
        p = unpack2(acc[i][3]); v[6] = p.x + bj[6]; v[7] = p.y + bj[7];
        if (tx < 7) {
            *(float4*)(g_k + (size_t)tok * DK + tx * 8)     = make_float4(v[0], v[1], v[2], v[3]);
            *(float4*)(g_k + (size_t)tok * DK + tx * 8 + 4) = make_float4(v[4], v[5], v[6], v[7]);
        } else if (tx == 7) {
            *(float4*)(g_k + (size_t)tok * DK + 56) = make_float4(v[0], v[1], v[2], v[3]);
        } else if (tx < 15) {
            *(float4*)(g_v + (size_t)tok * DV + tx * 8 - 64)     = make_float4(v[0], v[1], v[2], v[3]);
            *(float4*)(g_v + (size_t)tok * DV + tx * 8 - 64 + 4) = make_float4(v[4], v[5], v[6], v[7]);
        } else {
            *(float4*)(g_v + (size_t)tok * DV + 56) = make_float4(v[0], v[1], v[2], v[3]);
        }
        float sq = 0.f;
        if (tx < 7)  sq = v[0]*v[0]+v[1]*v[1]+v[2]*v[2]+v[3]*v[3]+v[4]*v[4]+v[5]*v[5]+v[6]*v[6]+v[7]*v[7];
        if (tx == 7) sq = v[0]*v[0]+v[1]*v[1]+v[2]*v[2]+v[3]*v[3];
#pragma unroll
        for (int o = 4; o; o >>= 1) sq += __shfl_xor_sync(0xffffffffu, sq, o);
        if (tx == 0) g_kn[tok] = sqrtf(sq);
    }
}

// ---------------------------------------------------------------------------
// attn: 64 q-rows/block x 512 ctx (8 tiles of 64), 256 threads, 4r x 4c tiles
// smem 70KB -> 3 CTAs/SM. Writes normalized attention output to g_ao.
// ---------------------------------------------------------------------------
__global__ void __launch_bounds__(256) attn_kernel(
    const float* __restrict__ pos_bias)
{
    extern __shared__ float sm[];
    float* Qt     = sm;                 // [60][72] swizzled
    float* KtT    = Qt + 60 * 72;       // [60][72] swizzled
    float* Vs     = KtT + 60 * 72;      // [64][64]
    float* Pt     = Vs + 64 * 64;       // [64][72] swizzled
    float* m_s    = Pt + 64 * 72;       // [64]
    float* l_s    = m_s + 64;           // [64]
    float* corr_s = l_s + 64;           // [64]

    const int b   = blockIdx.y;
    const int tq0 = blockIdx.x * 64;
    const int tid = threadIdx.x;
    const int tx  = tid & 15;           // c/dv group (c0 = tx*4)
    const int ty  = tid >> 4;           // row group (r0 = ty*4)
    const int r0  = ty * 4;

    // stage Qt (swizzled transpose)
    for (int idx = tid; idx < 64 * 16; idx += 256) {
        int t = idx >> 4, l = idx & 15;
        if (l < 15) {
            float4 q = *(const float4*)(g_q + (size_t)(b * NT + tq0 + t) * DK + l * 4);
            int ts = t ^ ((l & 7) << 2);
            Qt[(4 * l + 0) * 72 + ts] = q.x;
            Qt[(4 * l + 1) * 72 + ts] = q.y;
            Qt[(4 * l + 2) * 72 + ts] = q.z;
            Qt[(4 * l + 3) * 72 + ts] = q.w;
        }
    }
    if (tid < 64) { m_s[tid] = -1e30f; l_s[tid] = 0.f; }

    float qn_r[4];
#pragma unroll
    for (int i = 0; i < 4; i++) qn_r[i] = g_qn[b * NT + tq0 + r0 + i];

    u64 oa[4][2];
#pragma unroll
    for (int i = 0; i < 4; i++) { oa[i][0] = 0ull; oa[i][1] = 0ull; }

    for (int ct = 0; ct < 8; ct++) {
        const int cb = ct * 64;
        __syncthreads();
        for (int idx = tid; idx < 64 * 16; idx += 256) {
            int c = idx >> 4, l = idx & 15;
            if (l < 15) {
                float4 k4 = *(const float4*)(g_k + (size_t)(b * NC + cb + c) * DK + l * 4);
                int cs = c ^ ((l & 7) << 2);
                KtT[(4 * l + 0) * 72 + cs] = k4.x;
                KtT[(4 * l + 1) * 72 + cs] = k4.y;
                KtT[(4 * l + 2) * 72 + cs] = k4.z;
                KtT[(4 * l + 3) * 72 + cs] = k4.w;
            }
        }
        for (int idx = tid; idx < 64 * 16; idx += 256) {
            int c = idx >> 4, l = idx & 15;
            if (l < 15) {
                float4 v4 = *(const float4*)(g_v + (size_t)(b * NC + cb + c) * DV + l * 4);
                *(float4*)(Vs + c * 64 + l * 4) = v4;
            } else {
                *(float4*)(Vs + c * 64 + 60) = make_float4(0.f, 0.f, 0.f, 0.f);
            }
        }
        float kn_c[4], pb_c[4];
#pragma unroll
        for (int j = 0; j < 4; j++) {
            int c = tx * 4 + j;
            kn_c[j] = g_kn[b * NC + cb + c];
            pb_c[j] = pos_bias[cb + c];
        }
        __syncthreads();

        // scores 4r x 4c
        u64 s2[4][2];
#pragma unroll
        for (int i = 0; i < 4; i++) { s2[i][0] = 0ull; s2[i][1] = 0ull; }
#pragma unroll 4
        for (int k = 0; k < 60; k++) {
            int sw = ((k >> 2) & 7) << 2;
            float4 a4 = *(const float4*)(Qt + k * 72 + (r0 ^ sw));
            ulonglong2 b2 = *(const ulonglong2*)(KtT + k * 72 + ((tx * 4) ^ sw));
            float av[4] = {a4.x, a4.y, a4.z, a4.w};
#pragma unroll
            for (int i = 0; i < 4; i++) {
                u64 a = pack2(av[i]);
                ffma2(s2[i][0], a, b2.x);
                ffma2(s2[i][1], a, b2.y);
            }
        }
        float s[4][4];
#pragma unroll
        for (int i = 0; i < 4; i++) {
            float2 p0 = unpack2(s2[i][0]), p1 = unpack2(s2[i][1]);
            s[i][0] = p0.x; s[i][1] = p0.y; s[i][2] = p1.x; s[i][3] = p1.y;
        }

        // cosine + bias + online softmax (16 lanes per row group)
#pragma unroll
        for (int i = 0; i < 4; i++) {
            int r = r0 + i;
#pragma unroll
            for (int j = 0; j < 4; j++)
                s[i][j] = __fdividef(s[i][j], fmaxf(qn_r[i] * kn_c[j], EPSV)) + pb_c[j];
            float rm = fmaxf(fmaxf(s[i][0], s[i][1]), fmaxf(s[i][2], s[i][3]));
#pragma unroll
            for (int o = 8; o; o >>= 1) rm = fmaxf(rm, __shfl_xor_sync(0xffffffffu, rm, o));
            float mold = m_s[r];
            float newm = fmaxf(mold, rm);
            float corr = __expf(mold - newm);
            float sum = 0.f;
#pragma unroll
            for (int j = 0; j < 4; j++) {
                float p = __expf(s[i][j] - newm);
                s[i][j] = p;
                sum += p;
            }
#pragma unroll
            for (int o = 8; o; o >>= 1) sum += __shfl_xor_sync(0xffffffffu, sum, o);
            if (tx == 0) {
                m_s[r] = newm;
                l_s[r] = l_s[r] * corr + sum;
                corr_s[r] = corr;
            }
        }

        // P transposed (swizzled)
#pragma unroll
        for (int j = 0; j < 4; j++) {
            int c = tx * 4 + j;
            int swc = ((c >> 3) & 7) << 2;
            *(float4*)(Pt + c * 72 + (r0 ^ swc)) =
                make_float4(s[0][j], s[1][j], s[2][j], s[3][j]);
        }
        __syncthreads();

        // PV: 4r x 4dv
#pragma unroll
        for (int i = 0; i < 4; i++) {
            u64 cr = pack2(corr_s[r0 + i]);
            oa[i][0] = mul2(oa[i][0], cr);
            oa[i][1] = mul2(oa[i][1], cr);
        }
#pragma unroll 4
        for (int c = 0; c < 64; c++) {
            int swc = ((c >> 3) & 7) << 2;
            float4 p4 = *(const float4*)(Pt + c * 72 + (r0 ^ swc));
            ulonglong2 v2 = *(const ulonglong2*)(Vs + c * 64 + tx * 4);
            float pv[4] = {p4.x, p4.y, p4.z, p4.w};
#pragma unroll
            for (int i = 0; i < 4; i++) {
                u64 a = pack2(pv[i]);
                ffma2(oa[i][0], a, v2.x);
                ffma2(oa[i][1], a, v2.y);
            }
        }
    }

    if (tx < 15) {
#pragma unroll
        for (int i = 0; i < 4; i++) {
            float invl = __fdividef(1.f, l_s[r0 + i]);
            float2 p0 = unpack2(oa[i][0]), p1 = unpack2(oa[i][1]);
            *(float4*)(g_ao + (size_t)(b * NT + tq0 + r0 + i) * DV + tx * 4) =
                make_float4(p0.x * invl, p0.y * invl, p1.x * invl, p1.y * invl);
        }
    }
}

// ---------------------------------------------------------------------------
// proj_out: out[NTOK][256] = g_ao[NTOK][60] @ R_w^T + R_b
// 128t x 128e per block, 256 threads, 8x8 tiles. smem 65KB -> 2 CTAs.
// ---------------------------------------------------------------------------
__global__ void __launch_bounds__(256) proj_out_kernel(
    const float* __restrict__ R_w, const float* __restrict__ R_b,
    float* __restrict__ out)
{
    extern __shared__ float sm[];
    float* At = sm;                    // [60][136] swizzled
    float* Rt = At + 60 * 136;         // [60][136] swizzled

    const int tid = threadIdx.x;
    const int tx  = tid & 15;          // e0 = tx*8
    const int ty  = tid >> 4;          // t0 = ty*8
    const int t0g = blockIdx.x * 128;
    const int e0g = blockIdx.y * 128;

    for (int idx = tid; idx < 128 * 16; idx += 256) {
        int t = idx >> 4, l = idx & 15;
        if (l < 15) {
            float4 a = *(const float4*)(g_ao + (size_t)(t0g + t) * DV + l * 4);
            int ts = t ^ ((l & 7) << 2);
            At[(4 * l + 0) * 136 + ts] = a.x;
            At[(4 * l + 1) * 136 + ts] = a.y;
            At[(4 * l + 2) * 136 + ts] = a.z;
            At[(4 * l + 3) * 136 + ts] = a.w;
        }
    }
    for (int idx = tid; idx < 128 * 16; idx += 256) {
        int e = idx >> 4, l = idx & 15;
        if (l < 15) {
            float4 w = *(const float4*)(R_w + (size_t)(e0g + e) * DV + l * 4);
            int es = e ^ ((l & 7) << 2);
            Rt[(4 * l + 0) * 136 + es] = w.x;
            Rt[(4 * l + 1) * 136 + es] = w.y;
            Rt[(4 * l + 2) * 136 + es] = w.z;
            Rt[(4 * l + 3) * 136 + es] = w.w;
        }
    }
    __syncthreads();

    u64 acc[8][4];
#pragma unroll
    for (int i = 0; i < 8; i++)
#pragma unroll
        for (int j = 0; j < 4; j++) acc[i][j] = 0ull;

#pragma unroll 4
    for (int k = 0; k < 60; k++) {
        int sw = ((k >> 2) & 7) << 2;
        float4 a0 = *(const float4*)(At + k * 136 + ((ty * 8) ^ sw));
        float4 a1 = *(const float4*)(At + k * 136 + ((ty * 8 + 4) ^ sw));
        ulonglong2 b0 = *(const ulonglong2*)(Rt + k * 136 + ((tx * 8) ^ sw));
        ulonglong2 b1 = *(const ulonglong2*)(Rt + k * 136 + ((tx * 8 + 4) ^ sw));
        float av[8] = {a0.x, a0.y, a0.z, a0.w, a1.x, a1.y, a1.z, a1.w};
#pragma unroll
        for (int i = 0; i < 8; i++) {
            u64 a = pack2(av[i]);
            ffma2(acc[i][0], a, b0.x);
            ffma2(acc[i][1], a, b0.y);
            ffma2(acc[i][2], a, b1.x);
            ffma2(acc[i][3], a, b1.y);
        }
    }

    float4 rb0 = *(const float4*)(R_b + e0g + tx * 8);
    float4 rb1 = *(const float4*)(R_b + e0g + tx * 8 + 4);
#pragma unroll
    for (int i = 0; i < 8; i++) {
        size_t o = (size_t)(t0g + ty * 8 + i) * EMB + e0g + tx * 8;
        float2 p0 = unpack2(acc[i][0]), p1 = unpack2(acc[i][1]);
        float2 p2 = unpack2(acc[i][2]), p3 = unpack2(acc[i][3]);
        *(float4*)(out + o)     = make_float4(p0.x + rb0.x, p0.y + rb0.y, p1.x + rb0.z, p1.y + rb0.w);
        *(float4*)(out + o + 4) = make_float4(p2.x + rb1.x, p2.y + rb1.y, p3.x + rb1.z, p3.y + rb1.w);
    }
}

// ---------------------------------------------------------------------------
extern "C" void kernel_launch(void* const* d_in, const int* in_sizes, int n_in,
                              void* d_out, int out_size)
{
    const int*   titems   = (const int*)  d_in[0];
    const int*   citems   = (const int*)  d_in[1];
    const float* tvec     = (const float*)d_in[2];
    const float* cvec     = (const float*)d_in[3];
    const float* At_w     = (const float*)d_in[4];
    const float* At_b     = (const float*)d_in[5];
    const float* Ac_w     = (const float*)d_in[6];
    const float* Ac_b     = (const float*)d_in[7];
    const float* Bc_w     = (const float*)d_in[8];
    const float* Bc_b     = (const float*)d_in[9];
    const float* pos_bias = (const float*)d_in[10];
    const float* R_w      = (const float*)d_in[11];
    const float* R_b      = (const float*)d_in[12];
    float* out = (float*)d_out;

    const int smem_q   = (256 + 64 * 64 + 64 * 264) * 4;                     // 84992
    const int smem_kv  = (128 + 64 * 128 + 64 * 136) * 4;                    // 68096
    const int smem_at  = (60 * 72 * 2 + 64 * 64 + 64 * 72 + 192) * 4;        // 70144
    const int smem_out = (60 * 136 * 2) * 4;                                 // 65280

    cudaFuncSetAttribute(proj_q_kernel,   cudaFuncAttributeMaxDynamicSharedMemorySize, smem_q);
    cudaFuncSetAttribute(proj_kv_kernel,  cudaFuncAttributeMaxDynamicSharedMemorySize, smem_kv);
    cudaFuncSetAttribute(attn_kernel,     cudaFuncAttributeMaxDynamicSharedMemorySize, smem_at);
    cudaFuncSetAttribute(proj_out_kernel, cudaFuncAttributeMaxDynamicSharedMemorySize, smem_out);

    proj_q_kernel  <<< NTOK / 256,  256, smem_q  >>>(titems, tvec, At_w, At_b);
    proj_kv_kernel <<< NCTOK / 128, 256, smem_kv >>>(citems, cvec, Ac_w, Ac_b, Bc_w, Bc_b);
    attn_kernel    <<< dim3(NT / 64, BATCH), 256, smem_at >>>(pos_bias);
    proj_out_kernel<<< dim3(NTOK / 128, EMB / 128), 256, smem_out >>>(R_w, R_b, out);
}